// round 12
// baseline (speedup 1.0000x reference)
#include <cuda_runtime.h>

// RegionIntegrator — FINAL (best measured: 43.5us ncu, DRAM 82.0%,
// 6.49 TB/s, bench 47.6us, rel_err 0).
//
// Fixed geometry: B=4, N_REG=225 (15x15 grid, step 32), C=16, RS=64,
// H=W=512, pad=0. The reference's scatter-add + coverage-count division is
// inverted into a pure gather: each output pixel (i,j) is covered by at
// most 2x2 regions, whose starts are the multiples of 32 in [p-63, p]
// clamped to [0,448] per axis. Coverage count = (#row starts)*(#col starts)
// in {1,2,4} -> exact fp32 reciprocal. No atomics, no count buffer, orig_x
// unused. Each input byte is read exactly once (236 MB read + 67 MB write
// = minimal traffic).
//
// Tuning outcomes (11 rounds, all measured on GB300):
//  - 1 float4 quad per thread, block=256. Row-pairing (x2), block=512, and
//    Blackwell v8 256-bit ops all neutral/regressive: the kernel is pinned
//    at the chip's mixed-stream memory ceiling (~6.4-6.5 TB/s), with issue
//    utilization down to 18% having zero effect on duration.
//  - Default caching on loads (__ldcs measured -5% DRAM busy).
//  - Streaming store __stcs (output never re-read): +2.8% DRAM busy.

#define RI_B   4
#define RI_N   225
#define RI_C   16
#define RI_HW  512
#define RI_W4  128  // 512 / 4

__global__ __launch_bounds__(256) void region_gather_kernel(
    const float* __restrict__ regions, float* __restrict__ out)
{
    int idx = blockIdx.x * blockDim.x + threadIdx.x;   // over B*C*H*(W/4) = 4,194,304
    int j4 = (idx & (RI_W4 - 1)) << 2;                 // 0..508, multiple of 4
    int i  = (idx >> 7) & (RI_HW - 1);                 // 0..511
    int bc = idx >> 16;                                 // b*16 + c
    int c  = bc & (RI_C - 1);
    int b  = bc >> 4;

    // Covering row starts: multiples of 32 in [max(0,p-63), min(448,p)]
    int lo_i       = i - 63; if (lo_i < 0) lo_i = 0;
    int hi_i       = i < 448 ? i : 448;
    int s_first_i  = ((lo_i + 31) >> 5) << 5;
    int s_last_i   = (hi_i >> 5) << 5;

    int lo_j       = j4 - 63; if (lo_j < 0) lo_j = 0;
    int hi_j       = j4 < 448 ? j4 : 448;
    int s_first_j  = ((lo_j + 31) >> 5) << 5;
    int s_last_j   = (hi_j >> 5) << 5;

    bool two_i = (s_last_i != s_first_i);
    bool two_j = (s_last_j != s_first_j);

    // regions[((b*225 + n)*16 + c) * 4096 + ri*64 + rj]
    long base_bc = ((long)b * RI_N) * RI_C + c;

    float4 acc = make_float4(0.f, 0.f, 0.f, 0.f);

    {
        int n  = (s_first_i >> 5) * 15 + (s_first_j >> 5);
        long off = (base_bc + (long)n * RI_C) * 4096 + ((i - s_first_i) << 6) + (j4 - s_first_j);
        float4 v = *reinterpret_cast<const float4*>(regions + off);
        acc.x += v.x; acc.y += v.y; acc.z += v.z; acc.w += v.w;
    }
    if (two_j) {
        int n  = (s_first_i >> 5) * 15 + (s_last_j >> 5);
        long off = (base_bc + (long)n * RI_C) * 4096 + ((i - s_first_i) << 6) + (j4 - s_last_j);
        float4 v = *reinterpret_cast<const float4*>(regions + off);
        acc.x += v.x; acc.y += v.y; acc.z += v.z; acc.w += v.w;
    }
    if (two_i) {
        int n  = (s_last_i >> 5) * 15 + (s_first_j >> 5);
        long off = (base_bc + (long)n * RI_C) * 4096 + ((i - s_last_i) << 6) + (j4 - s_first_j);
        float4 v = *reinterpret_cast<const float4*>(regions + off);
        acc.x += v.x; acc.y += v.y; acc.z += v.z; acc.w += v.w;
    }
    if (two_i && two_j) {
        int n  = (s_last_i >> 5) * 15 + (s_last_j >> 5);
        long off = (base_bc + (long)n * RI_C) * 4096 + ((i - s_last_i) << 6) + (j4 - s_last_j);
        float4 v = *reinterpret_cast<const float4*>(regions + off);
        acc.x += v.x; acc.y += v.y; acc.z += v.z; acc.w += v.w;
    }

    int cnt = (two_i ? 2 : 1) * (two_j ? 2 : 1);   // 1, 2 or 4
    float inv = (cnt == 1) ? 1.0f : (cnt == 2 ? 0.5f : 0.25f);
    acc.x *= inv; acc.y *= inv; acc.z *= inv; acc.w *= inv;

    long oidx = ((long)bc * RI_HW + i) * RI_HW + j4;
    __stcs(reinterpret_cast<float4*>(out + oidx), acc);
}

extern "C" void kernel_launch(void* const* d_in, const int* in_sizes, int n_in,
                              void* d_out, int out_size)
{
    const float* regions = (const float*)d_in[0];
    float* out = (float*)d_out;
    int total = RI_B * RI_C * RI_HW * RI_W4;   // 4,194,304
    int block = 256;
    int grid = total / block;                  // 16384
    region_gather_kernel<<<grid, block>>>(regions, out);
}